// round 1
// baseline (speedup 1.0000x reference)
#include <cuda_runtime.h>
#include <math.h>

// Problem constants
#define BB   8
#define SS   2048
#define DD   1024
#define NN   1024
#define KK   1024
#define MM   (BB*SS)        // 16384

// ---------------------------------------------------------------------------
// Scratch (no cudaMalloc allowed) : 6 x 64 MiB
// ---------------------------------------------------------------------------
__device__ __align__(16) float g_u_re [(size_t)MM*NN];
__device__ __align__(16) float g_u_im [(size_t)MM*NN];
__device__ __align__(16) float g_hs_re[(size_t)MM*NN];
__device__ __align__(16) float g_hs_im[(size_t)MM*NN];
__device__ __align__(16) float g_y    [(size_t)MM*NN];
__device__ __align__(16) float g_g    [(size_t)MM*NN];
__device__ float g_lam[3*NN];   // [0..N) lam_re, [N..2N) lam_im, [2N..3N) gamma

// ---------------------------------------------------------------------------
// Per-channel recurrence parameters
// ---------------------------------------------------------------------------
__global__ void params_kernel(const float* __restrict__ nu_log,
                              const float* __restrict__ theta_log)
{
    int n = blockIdx.x * blockDim.x + threadIdx.x;
    if (n < NN) {
        float mag   = expf(-expf(nu_log[n]));
        float phase = expf(theta_log[n]);
        g_lam[n]        = mag * cosf(phase);
        g_lam[NN + n]   = mag * sinf(phase);
        g_lam[2*NN + n] = sqrtf(fmaxf(1.0f - mag*mag, 0.0f));
    }
}

// ---------------------------------------------------------------------------
// Generic NT SGEMM: C[M,Nout] = beta*C + alpha * (A[M,K] @ B[Nout,K]^T) * colscale
// Tile 128x128x16, 256 threads, 8x8 microtile, float4 global loads.
// M, Nout multiples of 128; K multiple of 16.
// ---------------------------------------------------------------------------
__global__ __launch_bounds__(256)
void sgemm_nt(const float* __restrict__ A, const float* __restrict__ Bm,
              float* __restrict__ C, int M, int Nout, int K,
              const float* __restrict__ colscale, float alpha, float beta)
{
    __shared__ float As[16][128];
    __shared__ float Bs[16][128];

    const int tid = threadIdx.x;
    const int tx  = tid & 15;        // 0..15 -> col group
    const int ty  = tid >> 4;        // 0..15 -> row group
    const int blockRow = blockIdx.y * 128;
    const int blockCol = blockIdx.x * 128;

    float acc[8][8];
    #pragma unroll
    for (int i = 0; i < 8; i++)
        #pragma unroll
        for (int j = 0; j < 8; j++) acc[i][j] = 0.0f;

    const int lr = tid >> 1;                 // load row 0..127
    const int c0 = (tid & 1) << 1;           // float4 col group {0,1} or {2,3}

    for (int kt = 0; kt < K; kt += 16) {
        #pragma unroll
        for (int q = 0; q < 2; q++) {
            int c4 = c0 + q;                 // 0..3
            float4 av = *(const float4*)&A [(size_t)(blockRow + lr) * K + kt + c4*4];
            As[c4*4+0][lr] = av.x; As[c4*4+1][lr] = av.y;
            As[c4*4+2][lr] = av.z; As[c4*4+3][lr] = av.w;
            float4 bv = *(const float4*)&Bm[(size_t)(blockCol + lr) * K + kt + c4*4];
            Bs[c4*4+0][lr] = bv.x; Bs[c4*4+1][lr] = bv.y;
            Bs[c4*4+2][lr] = bv.z; Bs[c4*4+3][lr] = bv.w;
        }
        __syncthreads();

        #pragma unroll
        for (int k = 0; k < 16; k++) {
            float a[8], b[8];
            *(float4*)&a[0] = *(const float4*)&As[k][ty*8];
            *(float4*)&a[4] = *(const float4*)&As[k][ty*8+4];
            *(float4*)&b[0] = *(const float4*)&Bs[k][tx*8];
            *(float4*)&b[4] = *(const float4*)&Bs[k][tx*8+4];
            #pragma unroll
            for (int i = 0; i < 8; i++)
                #pragma unroll
                for (int j = 0; j < 8; j++)
                    acc[i][j] = fmaf(a[i], b[j], acc[i][j]);
        }
        __syncthreads();
    }

    #pragma unroll
    for (int i = 0; i < 8; i++) {
        int row = blockRow + ty*8 + i;
        #pragma unroll
        for (int j = 0; j < 8; j++) {
            int col = blockCol + tx*8 + j;
            float v = alpha * acc[i][j];
            if (colscale) v *= colscale[col];
            size_t idx = (size_t)row * Nout + col;
            if (beta != 0.0f) v += C[idx];
            C[idx] = v;
        }
    }
}

// ---------------------------------------------------------------------------
// Sequential complex recurrence: one thread per (b, n) chain.
// Reads g_u_*, writes g_hs_*, writes final state into d_out tail.
// ---------------------------------------------------------------------------
__global__ void scan_kernel(const float* __restrict__ hid_re,
                            const float* __restrict__ hid_im,
                            float* __restrict__ out)
{
    int idx = blockIdx.x * blockDim.x + threadIdx.x;   // 0..B*N-1
    int b = idx >> 10;
    int n = idx & (NN - 1);
    const float lre = g_lam[n];
    const float lim = g_lam[NN + n];
    float hr = hid_re[idx];
    float hi = hid_im[idx];
    size_t off = (size_t)b * SS * NN + n;
    #pragma unroll 4
    for (int s = 0; s < SS; s++) {
        float ur = g_u_re[off];
        float ui = g_u_im[off];
        float nr = fmaf(lre, hr, fmaf(-lim, hi, ur));
        float ni = fmaf(lre, hi, fmaf( lim, hr, ui));
        g_hs_re[off] = nr;
        g_hs_im[off] = ni;
        hr = nr; hi = ni;
        off += NN;
    }
    out[(size_t)MM * DD + idx]            = hr;   // hf_re
    out[(size_t)MM * DD + BB*NN + idx]    = hi;   // hf_im
}

// ---------------------------------------------------------------------------
// Fused pointwise: z = gelu(LN(LN(y) * gelu(LN(g)))), written back into y.
// One 256-thread block per row of length N=1024 (4 elements/thread).
// ---------------------------------------------------------------------------
__device__ __forceinline__ float gelu_exact(float x)
{
    return 0.5f * x * (1.0f + erff(x * 0.70710678118654752f));
}

__device__ __forceinline__ void block_stats(float v0, float v1, float v2, float v3,
                                            float* sh, float& mu, float& rstd)
{
    float s  = v0 + v1 + v2 + v3;
    float s2 = v0*v0 + v1*v1 + v2*v2 + v3*v3;
    #pragma unroll
    for (int o = 16; o > 0; o >>= 1) {
        s  += __shfl_xor_sync(0xffffffffu, s,  o);
        s2 += __shfl_xor_sync(0xffffffffu, s2, o);
    }
    int w = threadIdx.x >> 5, l = threadIdx.x & 31;
    if (l == 0) { sh[w] = s; sh[8 + w] = s2; }
    __syncthreads();
    float ts = 0.f, ts2 = 0.f;
    #pragma unroll
    for (int i = 0; i < 8; i++) { ts += sh[i]; ts2 += sh[8 + i]; }
    __syncthreads();
    mu = ts * (1.0f / NN);
    float var = ts2 * (1.0f / NN) - mu * mu;
    rstd = rsqrtf(var + 1e-5f);
}

__global__ __launch_bounds__(256)
void pointwise_kernel(float* __restrict__ y, const float* __restrict__ g)
{
    __shared__ float sh[16];
    const size_t base = (size_t)blockIdx.x * NN;
    const int t = threadIdx.x;

    float yv[4], gv[4];
    #pragma unroll
    for (int q = 0; q < 4; q++) {
        yv[q] = y[base + t + q*256];
        gv[q] = g[base + t + q*256];
    }

    float mu, rstd;
    // LN(y)
    block_stats(yv[0], yv[1], yv[2], yv[3], sh, mu, rstd);
    #pragma unroll
    for (int q = 0; q < 4; q++) yv[q] = (yv[q] - mu) * rstd;
    // gate = gelu(LN(g))
    block_stats(gv[0], gv[1], gv[2], gv[3], sh, mu, rstd);
    #pragma unroll
    for (int q = 0; q < 4; q++) gv[q] = gelu_exact((gv[q] - mu) * rstd);
    // v = LN(y)*gate ; z = gelu(LN(v))
    #pragma unroll
    for (int q = 0; q < 4; q++) yv[q] *= gv[q];
    block_stats(yv[0], yv[1], yv[2], yv[3], sh, mu, rstd);
    #pragma unroll
    for (int q = 0; q < 4; q++)
        y[base + t + q*256] = gelu_exact((yv[q] - mu) * rstd);
}

// ---------------------------------------------------------------------------
// Launch
// ---------------------------------------------------------------------------
extern "C" void kernel_launch(void* const* d_in, const int* in_sizes, int n_in,
                              void* d_out, int out_size)
{
    const float* x         = (const float*)d_in[0];
    const float* hidden_re = (const float*)d_in[1];
    const float* hidden_im = (const float*)d_in[2];
    const float* nu_log    = (const float*)d_in[3];
    const float* theta_log = (const float*)d_in[4];
    const float* B_re      = (const float*)d_in[5];
    const float* B_im      = (const float*)d_in[6];
    const float* C_re      = (const float*)d_in[7];
    const float* C_im      = (const float*)d_in[8];
    const float* D_skip    = (const float*)d_in[9];
    const float* W_gate    = (const float*)d_in[10];
    const float* W_con     = (const float*)d_in[11];
    float* out = (float*)d_out;

    float *u_re, *u_im, *hs_re, *hs_im, *ybuf, *gbuf, *lam;
    cudaGetSymbolAddress((void**)&u_re,  g_u_re);
    cudaGetSymbolAddress((void**)&u_im,  g_u_im);
    cudaGetSymbolAddress((void**)&hs_re, g_hs_re);
    cudaGetSymbolAddress((void**)&hs_im, g_hs_im);
    cudaGetSymbolAddress((void**)&ybuf,  g_y);
    cudaGetSymbolAddress((void**)&gbuf,  g_g);
    cudaGetSymbolAddress((void**)&lam,   g_lam);
    const float* gamma = lam + 2*NN;

    params_kernel<<<1, 1024>>>(nu_log, theta_log);

    dim3 blk(256);
    dim3 grd(NN/128, MM/128);

    // u = (x @ B^T) * gamma   (complex)
    sgemm_nt<<<grd, blk>>>(x, B_re, u_re, MM, NN, KK, gamma, 1.0f, 0.0f);
    sgemm_nt<<<grd, blk>>>(x, B_im, u_im, MM, NN, KK, gamma, 1.0f, 0.0f);

    // sequential recurrence  h_t = lam*h_{t-1} + u_t
    scan_kernel<<<(BB*NN)/256, 256>>>(hidden_re, hidden_im, out);

    // y = hs_re@C_re^T - hs_im@C_im^T + x@D_skip^T
    sgemm_nt<<<grd, blk>>>(hs_re, C_re,   ybuf, MM, NN, KK, nullptr,  1.0f, 0.0f);
    sgemm_nt<<<grd, blk>>>(hs_im, C_im,   ybuf, MM, NN, KK, nullptr, -1.0f, 1.0f);
    sgemm_nt<<<grd, blk>>>(x,     D_skip, ybuf, MM, NN, KK, nullptr,  1.0f, 1.0f);

    // gate pre-activation
    sgemm_nt<<<grd, blk>>>(x, W_gate, gbuf, MM, NN, KK, nullptr, 1.0f, 0.0f);

    // fused LN/GELU chain (in-place into ybuf)
    pointwise_kernel<<<MM, 256>>>(ybuf, gbuf);

    // out = z @ W_con^T
    dim3 grdo(DD/128, MM/128);
    sgemm_nt<<<grdo, blk>>>(ybuf, W_con, out, MM, DD, NN, nullptr, 1.0f, 0.0f);
}

// round 4
// speedup vs baseline: 2.2212x; 2.2212x over previous
#include <cuda_runtime.h>
#include <cuda_bf16.h>
#include <math.h>
#include <stdint.h>

// Problem constants
#define BB   8
#define SS   2048
#define DD   1024
#define NN   1024
#define MM   (BB*SS)        // 16384
#define WSZ  (NN*DD)        // per weight matrix

// ---------------------------------------------------------------------------
// Scratch (no cudaMalloc allowed)
// ---------------------------------------------------------------------------
__device__ __align__(16) float g_u_re [(size_t)MM*NN];
__device__ __align__(16) float g_u_im [(size_t)MM*NN];
__device__ __align__(16) float g_y    [(size_t)MM*NN];
__device__ __align__(16) float g_g    [(size_t)MM*NN];
__device__ __align__(16) __nv_bfloat16 g_x_hi[(size_t)MM*DD];
__device__ __align__(16) __nv_bfloat16 g_x_lo[(size_t)MM*DD];
__device__ __align__(16) __nv_bfloat16 g_hsre_hi[(size_t)MM*NN];
__device__ __align__(16) __nv_bfloat16 g_hsre_lo[(size_t)MM*NN];
__device__ __align__(16) __nv_bfloat16 g_hsim_hi[(size_t)MM*NN];
__device__ __align__(16) __nv_bfloat16 g_hsim_lo[(size_t)MM*NN];
__device__ __align__(16) __nv_bfloat16 g_z_hi[(size_t)MM*NN];
__device__ __align__(16) __nv_bfloat16 g_z_lo[(size_t)MM*NN];
__device__ __align__(16) __nv_bfloat16 g_w_hi[(size_t)7*WSZ];
__device__ __align__(16) __nv_bfloat16 g_w_lo[(size_t)7*WSZ];
__device__ float g_lam[3*NN];   // lam_re, lam_im, gamma

// ---------------------------------------------------------------------------
// Baseline-PTX helpers (NO arch-specific instructions: compute_103-safe)
// ---------------------------------------------------------------------------
__device__ __forceinline__ uint32_t smem_u32(const void* p) {
    uint32_t a;
    asm("{ .reg .u64 t; cvta.to.shared.u64 t, %1; cvt.u32.u64 %0, t; }"
        : "=r"(a) : "l"(p));
    return a;
}
#define CP_ASYNC16(dst, src) \
    asm volatile("cp.async.cg.shared.global [%0], [%1], 16;" :: "r"(dst), "l"(src) : "memory")
#define CP_COMMIT() asm volatile("cp.async.commit_group;" ::: "memory")
#define CP_WAIT1()  asm volatile("cp.async.wait_group 1;"  ::: "memory")

#define LDMX4(r0,r1,r2,r3,addr) \
    asm volatile("ldmatrix.sync.aligned.m8n8.x4.shared.b16 {%0,%1,%2,%3}, [%4];" \
        : "=r"(r0),"=r"(r1),"=r"(r2),"=r"(r3) : "r"(addr))

#define MMA16816(c, a, b) \
    asm volatile("mma.sync.aligned.m16n8k16.row.col.f32.bf16.bf16.f32 " \
        "{%0,%1,%2,%3}, {%4,%5,%6,%7}, {%8,%9}, {%0,%1,%2,%3};" \
        : "+f"((c)[0]),"+f"((c)[1]),"+f"((c)[2]),"+f"((c)[3]) \
        : "r"((a)[0]),"r"((a)[1]),"r"((a)[2]),"r"((a)[3]), \
          "r"((b)[0]),"r"((b)[1]))

// ---------------------------------------------------------------------------
// mma.sync GEMM:  C[M,Nout] = sum_t (Ahi+Alo)_t @ (Bhi+Blo)_t^T  (lo*lo dropped)
// 128x128 tile, BK=32, 256 threads (8 warps: 2x4, warp tile 64x32),
// 3-stage cp.async pipeline, 80B-padded smem rows (ldmatrix conflict-free).
// ---------------------------------------------------------------------------
struct GemmTerm { const __nv_bfloat16 *a_hi, *a_lo, *b_hi, *b_lo; };
struct GemmParams { GemmTerm t[3]; int nterms; };

#define ROWB   80                   // padded row bytes for 32 bf16 (64B data)
#define TILEB  (128*ROWB)           // 10240 bytes per operand tile
#define STAGEB (2*TILEB)            // 20480 per stage
#define GEMM_SMEM (3*STAGEB)        // 61440

__global__ __launch_bounds__(256, 2)
void gemm_mma(GemmParams p, float* __restrict__ C, int Nout,
              const float* __restrict__ colscale)
{
    extern __shared__ char smem[];
    const uint32_t sbase = smem_u32(smem);
    const int tid = threadIdx.x;
    const int lid = tid & 31, wid = tid >> 5;
    const int wm = (wid >> 2) * 64;        // warp M offset (0/64)
    const int wn = (wid & 3) * 32;         // warp N offset (0..96)
    const size_t rowA0 = (size_t)blockIdx.y * 128;
    const size_t rowB0 = (size_t)blockIdx.x * 128;
    const int KT = p.nterms * 32;          // k16-pairs: BK=32 elems per step

    const char* Asel[3]; const char* Bsel[3];
    // term order: hi*hi, hi*lo, lo*hi
    Asel[0] = (const char*)p.t[0].a_hi;  Bsel[0] = (const char*)p.t[0].b_hi;
    #pragma unroll
    for (int t = 1; t < 3; t++) { Asel[t] = Asel[0]; Bsel[t] = Bsel[0]; }
    if (p.nterms == 3) {
        Asel[0] = (const char*)p.t[0].a_hi;  Bsel[0] = (const char*)p.t[0].b_hi;
        Asel[1] = (const char*)p.t[1].a_hi;  Bsel[1] = (const char*)p.t[1].b_hi;
        Asel[2] = (const char*)p.t[2].a_hi;  Bsel[2] = (const char*)p.t[2].b_hi;
    }

    float acc[4][4][4];
    #pragma unroll
    for (int i = 0; i < 4; i++)
        #pragma unroll
        for (int j = 0; j < 4; j++)
            #pragma unroll
            for (int q = 0; q < 4; q++) acc[i][j][q] = 0.0f;

    // For the hi/lo split each "term slot" runs K=1024 over 3 sub-terms when
    // nterms==1: (Ahi,Bhi),(Ahi,Blo),(Alo,Bhi).  When nterms==3 the three
    // logical terms each contribute their own 3 sub-terms -> KT = nterms*3*32? 
    // To keep KT manageable we enumerate sub-terms explicitly below.
    // subsel[s] = pair of pointers for sub-term s; nsub = nterms*3.
    const char* subA[9]; const char* subB[9];
    int nsub = 0;
    #pragma unroll
    for (int t = 0; t < 3; t++) {
        if (t < p.nterms) {
            subA[nsub]   = (const char*)p.t[t].a_hi; subB[nsub]   = (const char*)p.t[t].b_hi;
            subA[nsub+1] = (const char*)p.t[t].a_hi; subB[nsub+1] = (const char*)p.t[t].b_lo;
            subA[nsub+2] = (const char*)p.t[t].a_lo; subB[nsub+2] = (const char*)p.t[t].b_hi;
            nsub += 3;
        }
    }
    const int KTOT = nsub * 32;            // total BK=32 steps

    // ---- stage loader: 2 x 16B chunks per thread per operand tile ----------
    auto load_stage = [&](int stage, int kIdx) {
        const char* Ap = subA[kIdx >> 5];
        const char* Bp = subB[kIdx >> 5];
        const int kb = (kIdx & 31) * 64;   // byte offset along K (32 bf16)
        const uint32_t sA = sbase + stage * STAGEB;
        const uint32_t sB = sA + TILEB;
        #pragma unroll
        for (int i = 0; i < 2; i++) {
            int c = tid + i * 256;         // 0..511
            int r = c >> 2;                // row 0..127
            int cc = (c & 3) * 16;         // 0/16/32/48 bytes
            CP_ASYNC16(sA + r * ROWB + cc, Ap + (rowA0 + r) * 2048 + kb + cc);
            CP_ASYNC16(sB + r * ROWB + cc, Bp + (rowB0 + r) * 2048 + kb + cc);
        }
    };

    auto compute_stage = [&](int stage) {
        const uint32_t sA = sbase + stage * STAGEB;
        const uint32_t sB = sA + TILEB;
        #pragma unroll
        for (int kh = 0; kh < 2; kh++) {   // two k16 halves of BK=32
            uint32_t a[4][4], b[4][2];
            #pragma unroll
            for (int mt = 0; mt < 4; mt++) {
                uint32_t ad = sA + (uint32_t)(wm + mt*16 + (lid & 15)) * ROWB
                            + kh * 32 + ((lid & 16) ? 16 : 0);
                LDMX4(a[mt][0], a[mt][1], a[mt][2], a[mt][3], ad);
            }
            #pragma unroll
            for (int np = 0; np < 2; np++) {   // each x4 covers two n8 tiles
                uint32_t bd = sB + (uint32_t)(wn + np*16 + ((lid >> 4) & 1) * 8
                            + (lid & 7)) * ROWB
                            + kh * 32 + (((lid >> 3) & 1) ? 16 : 0);
                uint32_t r0, r1, r2, r3;
                LDMX4(r0, r1, r2, r3, bd);
                b[np*2][0]   = r0; b[np*2][1]   = r1;
                b[np*2+1][0] = r2; b[np*2+1][1] = r3;
            }
            #pragma unroll
            for (int mt = 0; mt < 4; mt++)
                #pragma unroll
                for (int nt = 0; nt < 4; nt++)
                    MMA16816(acc[mt][nt], a[mt], b[nt]);
        }
    };

    // ---- pipelined main loop ----------------------------------------------
    load_stage(0, 0); CP_COMMIT();
    load_stage(1, 1); CP_COMMIT();
    for (int k = 0; k < KTOT; k++) {
        CP_WAIT1();
        __syncthreads();
        if (k + 2 < KTOT) load_stage((k + 2) % 3, k + 2);
        CP_COMMIT();
        compute_stage(k % 3);
    }

    // ---- epilogue: direct float2 stores -----------------------------------
    const int blockRow = blockIdx.y * 128;
    const int blockCol = blockIdx.x * 128;
    #pragma unroll
    for (int nt = 0; nt < 4; nt++) {
        int j = blockCol + wn + nt * 8 + (lid & 3) * 2;
        float cs0 = colscale ? colscale[j]     : 1.0f;
        float cs1 = colscale ? colscale[j + 1] : 1.0f;
        #pragma unroll
        for (int mt = 0; mt < 4; mt++) {
            int r = blockRow + wm + mt * 16 + (lid >> 2);
            float2 v0 = { acc[mt][nt][0] * cs0, acc[mt][nt][1] * cs1 };
            float2 v1 = { acc[mt][nt][2] * cs0, acc[mt][nt][3] * cs1 };
            *(float2*)&C[(size_t)r * Nout + j]       = v0;
            *(float2*)&C[(size_t)(r + 8) * Nout + j] = v1;
        }
    }
}

// ---------------------------------------------------------------------------
// Per-channel recurrence parameters
// ---------------------------------------------------------------------------
__global__ void params_kernel(const float* __restrict__ nu_log,
                              const float* __restrict__ theta_log)
{
    int n = blockIdx.x * blockDim.x + threadIdx.x;
    if (n < NN) {
        float mag   = expf(-expf(nu_log[n]));
        float phase = expf(theta_log[n]);
        g_lam[n]        = mag * cosf(phase);
        g_lam[NN + n]   = mag * sinf(phase);
        g_lam[2*NN + n] = sqrtf(fmaxf(1.0f - mag*mag, 0.0f));
    }
}

// ---------------------------------------------------------------------------
// fp32 -> (bf16 hi, bf16 lo)
// ---------------------------------------------------------------------------
__global__ void cvt_kernel(const float* __restrict__ src,
                           __nv_bfloat16* __restrict__ hi,
                           __nv_bfloat16* __restrict__ lo,
                           int n, float scale)
{
    int i = blockIdx.x * blockDim.x + threadIdx.x;
    if (i < n) {
        float v = src[i] * scale;
        __nv_bfloat16 h = __float2bfloat16(v);
        hi[i] = h;
        lo[i] = __float2bfloat16(v - __bfloat162float(h));
    }
}

// ---------------------------------------------------------------------------
// Sequential complex recurrence -> hi/lo bf16 states + final state in out tail
// ---------------------------------------------------------------------------
__global__ void scan_kernel(const float* __restrict__ hid_re,
                            const float* __restrict__ hid_im,
                            float* __restrict__ out)
{
    int idx = blockIdx.x * blockDim.x + threadIdx.x;   // 0..B*N-1
    int b = idx >> 10;
    int n = idx & (NN - 1);
    const float lre = g_lam[n];
    const float lim = g_lam[NN + n];
    float hr = hid_re[idx];
    float hi = hid_im[idx];
    size_t off = (size_t)b * SS * NN + n;
    #pragma unroll 4
    for (int s = 0; s < SS; s++) {
        float ur = g_u_re[off];
        float ui = g_u_im[off];
        float nr = fmaf(lre, hr, fmaf(-lim, hi, ur));
        float ni = fmaf(lre, hi, fmaf( lim, hr, ui));
        __nv_bfloat16 rh = __float2bfloat16(nr);
        __nv_bfloat16 ih = __float2bfloat16(ni);
        g_hsre_hi[off] = rh;
        g_hsre_lo[off] = __float2bfloat16(nr - __bfloat162float(rh));
        g_hsim_hi[off] = ih;
        g_hsim_lo[off] = __float2bfloat16(ni - __bfloat162float(ih));
        hr = nr; hi = ni;
        off += NN;
    }
    out[(size_t)MM * DD + idx]         = hr;   // hf_re
    out[(size_t)MM * DD + BB*NN + idx] = hi;   // hf_im
}

// ---------------------------------------------------------------------------
// Fused pointwise: z = gelu(LN(LN(y) * gelu(LN(g)))) -> bf16 hi/lo
// ---------------------------------------------------------------------------
__device__ __forceinline__ float gelu_exact(float x)
{
    return 0.5f * x * (1.0f + erff(x * 0.70710678118654752f));
}
__device__ __forceinline__ void block_stats(float v0, float v1, float v2, float v3,
                                            float* sh, float& mu, float& rstd)
{
    float s  = v0 + v1 + v2 + v3;
    float s2 = v0*v0 + v1*v1 + v2*v2 + v3*v3;
    #pragma unroll
    for (int o = 16; o > 0; o >>= 1) {
        s  += __shfl_xor_sync(0xffffffffu, s,  o);
        s2 += __shfl_xor_sync(0xffffffffu, s2, o);
    }
    int w = threadIdx.x >> 5, l = threadIdx.x & 31;
    if (l == 0) { sh[w] = s; sh[8 + w] = s2; }
    __syncthreads();
    float ts = 0.f, ts2 = 0.f;
    #pragma unroll
    for (int i = 0; i < 8; i++) { ts += sh[i]; ts2 += sh[8 + i]; }
    __syncthreads();
    mu = ts * (1.0f / NN);
    float var = ts2 * (1.0f / NN) - mu * mu;
    rstd = rsqrtf(var + 1e-5f);
}

__global__ __launch_bounds__(256)
void pointwise_kernel(const float* __restrict__ y, const float* __restrict__ g)
{
    __shared__ float sh[16];
    const size_t base = (size_t)blockIdx.x * NN;
    const int t = threadIdx.x;

    float yv[4], gv[4];
    #pragma unroll
    for (int q = 0; q < 4; q++) {
        yv[q] = y[base + t + q*256];
        gv[q] = g[base + t + q*256];
    }
    float mu, rstd;
    block_stats(yv[0], yv[1], yv[2], yv[3], sh, mu, rstd);
    #pragma unroll
    for (int q = 0; q < 4; q++) yv[q] = (yv[q] - mu) * rstd;
    block_stats(gv[0], gv[1], gv[2], gv[3], sh, mu, rstd);
    #pragma unroll
    for (int q = 0; q < 4; q++) gv[q] = gelu_exact((gv[q] - mu) * rstd);
    #pragma unroll
    for (int q = 0; q < 4; q++) yv[q] *= gv[q];
    block_stats(yv[0], yv[1], yv[2], yv[3], sh, mu, rstd);
    #pragma unroll
    for (int q = 0; q < 4; q++) {
        float z = gelu_exact((yv[q] - mu) * rstd);
        __nv_bfloat16 zh = __float2bfloat16(z);
        g_z_hi[base + t + q*256] = zh;
        g_z_lo[base + t + q*256] = __float2bfloat16(z - __bfloat162float(zh));
    }
}

// ---------------------------------------------------------------------------
// Launch
// ---------------------------------------------------------------------------
extern "C" void kernel_launch(void* const* d_in, const int* in_sizes, int n_in,
                              void* d_out, int out_size)
{
    const float* x         = (const float*)d_in[0];
    const float* hidden_re = (const float*)d_in[1];
    const float* hidden_im = (const float*)d_in[2];
    const float* nu_log    = (const float*)d_in[3];
    const float* theta_log = (const float*)d_in[4];
    const float* W[7] = { (const float*)d_in[5],  (const float*)d_in[6],
                          (const float*)d_in[7],  (const float*)d_in[8],
                          (const float*)d_in[9],  (const float*)d_in[10],
                          (const float*)d_in[11] };
    float* out = (float*)d_out;

    float *u_re, *u_im, *ybuf, *gbuf, *lam;
    __nv_bfloat16 *x_hi, *x_lo, *hsre_hi, *hsre_lo, *hsim_hi, *hsim_lo,
                  *z_hi, *z_lo, *w_hi, *w_lo;
    cudaGetSymbolAddress((void**)&u_re,    g_u_re);
    cudaGetSymbolAddress((void**)&u_im,    g_u_im);
    cudaGetSymbolAddress((void**)&ybuf,    g_y);
    cudaGetSymbolAddress((void**)&gbuf,    g_g);
    cudaGetSymbolAddress((void**)&x_hi,    g_x_hi);
    cudaGetSymbolAddress((void**)&x_lo,    g_x_lo);
    cudaGetSymbolAddress((void**)&hsre_hi, g_hsre_hi);
    cudaGetSymbolAddress((void**)&hsre_lo, g_hsre_lo);
    cudaGetSymbolAddress((void**)&hsim_hi, g_hsim_hi);
    cudaGetSymbolAddress((void**)&hsim_lo, g_hsim_lo);
    cudaGetSymbolAddress((void**)&z_hi,    g_z_hi);
    cudaGetSymbolAddress((void**)&z_lo,    g_z_lo);
    cudaGetSymbolAddress((void**)&w_hi,    g_w_hi);
    cudaGetSymbolAddress((void**)&w_lo,    g_w_lo);
    cudaGetSymbolAddress((void**)&lam,     g_lam);
    const float* gamma = lam + 2*NN;

    cudaFuncSetAttribute(gemm_mma, cudaFuncAttributeMaxDynamicSharedMemorySize, GEMM_SMEM);

    params_kernel<<<1, 1024>>>(nu_log, theta_log);

    // conversions
    cvt_kernel<<<(MM*DD + 255)/256, 256>>>(x, x_hi, x_lo, MM*DD, 1.0f);
    for (int w = 0; w < 7; w++)
        cvt_kernel<<<(WSZ + 255)/256, 256>>>(W[w], w_hi + (size_t)w*WSZ, w_lo + (size_t)w*WSZ,
                                             WSZ, (w == 3) ? -1.0f : 1.0f);  // negate C_im

    dim3 grd(NN / 128, MM / 128);   // (8, 128)

    // u = (x @ B^T) * gamma
    GemmParams pr;
    pr.nterms = 1;
    pr.t[0] = { x_hi, x_lo, w_hi + 0*WSZ, w_lo + 0*WSZ };
    gemm_mma<<<grd, 256, GEMM_SMEM>>>(pr, u_re, NN, gamma);
    pr.t[0] = { x_hi, x_lo, w_hi + 1*WSZ, w_lo + 1*WSZ };
    gemm_mma<<<grd, 256, GEMM_SMEM>>>(pr, u_im, NN, gamma);

    // recurrence (writes hs hi/lo + final state)
    scan_kernel<<<(BB*NN)/256, 256>>>(hidden_re, hidden_im, out);

    // y = hs_re@C_re^T - hs_im@C_im^T + x@D_skip^T  (C_im pre-negated)
    GemmParams py;
    py.nterms = 3;
    py.t[0] = { hsre_hi, hsre_lo, w_hi + 2*WSZ, w_lo + 2*WSZ };
    py.t[1] = { hsim_hi, hsim_lo, w_hi + 3*WSZ, w_lo + 3*WSZ };
    py.t[2] = { x_hi,    x_lo,    w_hi + 4*WSZ, w_lo + 4*WSZ };
    gemm_mma<<<grd, 256, GEMM_SMEM>>>(py, ybuf, NN, nullptr);

    // gate pre-activation
    GemmParams pg;
    pg.nterms = 1;
    pg.t[0] = { x_hi, x_lo, w_hi + 5*WSZ, w_lo + 5*WSZ };
    gemm_mma<<<grd, 256, GEMM_SMEM>>>(pg, gbuf, NN, nullptr);

    // fused LN/GELU chain -> z hi/lo
    pointwise_kernel<<<MM, 256>>>(ybuf, gbuf);

    // out = z @ W_con^T
    GemmParams po;
    po.nterms = 1;
    po.t[0] = { z_hi, z_lo, w_hi + 6*WSZ, w_lo + 6*WSZ };
    gemm_mma<<<dim3(DD / 128, MM / 128), 256, GEMM_SMEM>>>(po, out, DD, nullptr);
}

// round 6
// speedup vs baseline: 3.0946x; 1.3932x over previous
#include <cuda_runtime.h>
#include <cuda_bf16.h>
#include <math.h>
#include <stdint.h>

// Problem constants
#define BB   8
#define SS   2048
#define DD   1024
#define NN   1024
#define MM   (BB*SS)        // 16384
#define WSZ  (NN*DD)        // per weight matrix

// ---------------------------------------------------------------------------
// Scratch (no cudaMalloc allowed)
// ---------------------------------------------------------------------------
__device__ __align__(16) float g_u_re [(size_t)MM*NN];
__device__ __align__(16) float g_u_im [(size_t)MM*NN];
__device__ __align__(16) float g_y    [(size_t)MM*NN];
__device__ __align__(16) float g_g    [(size_t)MM*NN];
__device__ __align__(16) __nv_bfloat16 g_x_hi[(size_t)MM*DD];
__device__ __align__(16) __nv_bfloat16 g_x_lo[(size_t)MM*DD];
__device__ __align__(16) __nv_bfloat16 g_hsre_hi[(size_t)MM*NN];
__device__ __align__(16) __nv_bfloat16 g_hsre_lo[(size_t)MM*NN];
__device__ __align__(16) __nv_bfloat16 g_hsim_hi[(size_t)MM*NN];
__device__ __align__(16) __nv_bfloat16 g_hsim_lo[(size_t)MM*NN];
__device__ __align__(16) __nv_bfloat16 g_z_hi[(size_t)MM*NN];
__device__ __align__(16) __nv_bfloat16 g_z_lo[(size_t)MM*NN];
__device__ __align__(16) __nv_bfloat16 g_w_hi[(size_t)7*WSZ];
__device__ __align__(16) __nv_bfloat16 g_w_lo[(size_t)7*WSZ];
__device__ float g_lam[3*NN];   // lam_re, lam_im, gamma

// ---------------------------------------------------------------------------
// Baseline-PTX helpers (compute_103-safe: no tcgen05)
// ---------------------------------------------------------------------------
__device__ __forceinline__ uint32_t smem_u32(const void* p) {
    uint32_t a;
    asm("{ .reg .u64 t; cvta.to.shared.u64 t, %1; cvt.u32.u64 %0, t; }"
        : "=r"(a) : "l"(p));
    return a;
}
#define CP_ASYNC16(dst, src) \
    asm volatile("cp.async.cg.shared.global [%0], [%1], 16;" :: "r"(dst), "l"(src) : "memory")
#define CP_COMMIT() asm volatile("cp.async.commit_group;" ::: "memory")
#define CP_WAIT1()  asm volatile("cp.async.wait_group 1;"  ::: "memory")

#define LDMX4(r0,r1,r2,r3,addr) \
    asm volatile("ldmatrix.sync.aligned.m8n8.x4.shared.b16 {%0,%1,%2,%3}, [%4];" \
        : "=r"(r0),"=r"(r1),"=r"(r2),"=r"(r3) : "r"(addr))

#define MMA16816(c, a, b) \
    asm volatile("mma.sync.aligned.m16n8k16.row.col.f32.bf16.bf16.f32 " \
        "{%0,%1,%2,%3}, {%4,%5,%6,%7}, {%8,%9}, {%0,%1,%2,%3};" \
        : "+f"((c)[0]),"+f"((c)[1]),"+f"((c)[2]),"+f"((c)[3]) \
        : "r"((a)[0]),"r"((a)[1]),"r"((a)[2]),"r"((a)[3]), \
          "r"((b)[0]),"r"((b)[1]))

// ---------------------------------------------------------------------------
// Shared GEMM machinery: 128x128 tile, BK=32, 256 threads (8 warps 2x4,
// warp tile 64x32), 3-stage cp.async pipeline, 80B-padded rows.
// ---------------------------------------------------------------------------
#define ROWB   80
#define TILEB  (128*ROWB)           // 10240
#define STAGEB (2*TILEB)            // 20480
#define GEMM_SMEM (3*STAGEB)        // 61440

struct GemmCore {
    uint32_t sbase;
    int tid, lid, wid, wm, wn;
    size_t rowA0, rowB0;
    float acc[4][4][4];

    __device__ __forceinline__ void init(uint32_t sb, size_t ra0, size_t rb0) {
        sbase = sb;
        tid = threadIdx.x; lid = tid & 31; wid = tid >> 5;
        wm = (wid >> 2) * 64; wn = (wid & 3) * 32;
        rowA0 = ra0; rowB0 = rb0;
        #pragma unroll
        for (int i = 0; i < 4; i++)
            #pragma unroll
            for (int j = 0; j < 4; j++)
                #pragma unroll
                for (int q = 0; q < 4; q++) acc[i][j][q] = 0.0f;
    }

    __device__ __forceinline__ void load_stage(int stage, const char* Ap,
                                               const char* Bp, int kb) {
        const uint32_t sA = sbase + stage * STAGEB;
        const uint32_t sB = sA + TILEB;
        #pragma unroll
        for (int i = 0; i < 2; i++) {
            int c = tid + i * 256;
            int r = c >> 2;
            int cc = (c & 3) * 16;
            CP_ASYNC16(sA + r * ROWB + cc, Ap + (rowA0 + r) * 2048 + kb + cc);
            CP_ASYNC16(sB + r * ROWB + cc, Bp + (rowB0 + r) * 2048 + kb + cc);
        }
    }

    __device__ __forceinline__ void compute_stage(int stage) {
        const uint32_t sA = sbase + stage * STAGEB;
        const uint32_t sB = sA + TILEB;
        #pragma unroll
        for (int kh = 0; kh < 2; kh++) {
            uint32_t a[4][4], b[4][2];
            #pragma unroll
            for (int mt = 0; mt < 4; mt++) {
                uint32_t ad = sA + (uint32_t)(wm + mt*16 + (lid & 15)) * ROWB
                            + kh * 32 + ((lid & 16) ? 16 : 0);
                LDMX4(a[mt][0], a[mt][1], a[mt][2], a[mt][3], ad);
            }
            #pragma unroll
            for (int np = 0; np < 2; np++) {
                uint32_t bd = sB + (uint32_t)(wn + np*16 + ((lid >> 4) & 1) * 8
                            + (lid & 7)) * ROWB
                            + kh * 32 + (((lid >> 3) & 1) ? 16 : 0);
                uint32_t r0, r1, r2, r3;
                LDMX4(r0, r1, r2, r3, bd);
                b[np*2][0]   = r0; b[np*2][1]   = r1;
                b[np*2+1][0] = r2; b[np*2+1][1] = r3;
            }
            #pragma unroll
            for (int mt = 0; mt < 4; mt++)
                #pragma unroll
                for (int nt = 0; nt < 4; nt++)
                    MMA16816(acc[mt][nt], a[mt], b[nt]);
        }
    }

    __device__ __forceinline__ void run(const char* const* subA,
                                        const char* const* subB, int nsub) {
        const int KTOT = nsub * 32;
        load_stage(0, subA[0], subB[0], 0); CP_COMMIT();
        load_stage(1, subA[0], subB[0], 64); CP_COMMIT();
        for (int k = 0; k < KTOT; k++) {
            CP_WAIT1();
            __syncthreads();
            int kn = k + 2;
            if (kn < KTOT) load_stage(kn % 3, subA[kn >> 5], subB[kn >> 5],
                                      (kn & 31) * 64);
            CP_COMMIT();
            compute_stage(k % 3);
        }
    }

    __device__ __forceinline__ void epilogue(float* C, int Nout, int tileN,
                                             const float* colscale) {
        const int blockRow = blockIdx.y * 128;
        const int blockCol = tileN * 128;
        #pragma unroll
        for (int nt = 0; nt < 4; nt++) {
            int jl = wn + nt * 8 + (lid & 3) * 2;       // 0..127 within tile
            int j = blockCol + jl;
            float cs0 = colscale ? colscale[j]     : 1.0f;
            float cs1 = colscale ? colscale[j + 1] : 1.0f;
            #pragma unroll
            for (int mt = 0; mt < 4; mt++) {
                int r = blockRow + wm + mt * 16 + (lid >> 2);
                float2 v0 = { acc[mt][nt][0] * cs0, acc[mt][nt][1] * cs1 };
                float2 v1 = { acc[mt][nt][2] * cs0, acc[mt][nt][3] * cs1 };
                *(float2*)&C[(size_t)r * Nout + j]       = v0;
                *(float2*)&C[(size_t)(r + 8) * Nout + j] = v1;
            }
        }
    }
};

// ---------------------------------------------------------------------------
// Multi-job GEMM: shared A, per-tile-group B/out/colscale.
// grid.x = 8*njobs, job g = blockIdx.x>>3. 3 sub-terms (hi*hi, hi*lo, lo*hi).
// ---------------------------------------------------------------------------
struct Job { const __nv_bfloat16 *b_hi, *b_lo; float* out; const float* cs; };
struct MultiParams { const __nv_bfloat16 *a_hi, *a_lo; Job jobs[3]; };

__global__ __launch_bounds__(256, 2)
void gemm_multi(MultiParams p, int Nout)
{
    extern __shared__ char smem[];
    const int g = blockIdx.x >> 3;
    const int tileN = blockIdx.x & 7;
    const Job jb = p.jobs[g];

    GemmCore core;
    core.init(smem_u32(smem), (size_t)blockIdx.y * 128, (size_t)tileN * 128);

    const char* subA[3] = { (const char*)p.a_hi, (const char*)p.a_hi,
                            (const char*)p.a_lo };
    const char* subB[3] = { (const char*)jb.b_hi, (const char*)jb.b_lo,
                            (const char*)jb.b_hi };
    core.run(subA, subB, 3);
    core.epilogue(jb.out, Nout, tileN, jb.cs);
}

// ---------------------------------------------------------------------------
// 3-term GEMM (y): per-term A and B, 9 sub-terms.
// ---------------------------------------------------------------------------
struct GemmTerm { const __nv_bfloat16 *a_hi, *a_lo, *b_hi, *b_lo; };
struct YParams { GemmTerm t[3]; };

__global__ __launch_bounds__(256, 2)
void gemm_y(YParams p, float* __restrict__ C, int Nout)
{
    extern __shared__ char smem[];
    const int tileN = blockIdx.x;

    GemmCore core;
    core.init(smem_u32(smem), (size_t)blockIdx.y * 128, (size_t)tileN * 128);

    const char* subA[9]; const char* subB[9];
    #pragma unroll
    for (int t = 0; t < 3; t++) {
        subA[3*t]   = (const char*)p.t[t].a_hi; subB[3*t]   = (const char*)p.t[t].b_hi;
        subA[3*t+1] = (const char*)p.t[t].a_hi; subB[3*t+1] = (const char*)p.t[t].b_lo;
        subA[3*t+2] = (const char*)p.t[t].a_lo; subB[3*t+2] = (const char*)p.t[t].b_hi;
    }
    core.run(subA, subB, 9);
    core.epilogue(C, Nout, tileN, nullptr);
}

// ---------------------------------------------------------------------------
// Per-channel recurrence parameters
// ---------------------------------------------------------------------------
__global__ void params_kernel(const float* __restrict__ nu_log,
                              const float* __restrict__ theta_log)
{
    int n = blockIdx.x * blockDim.x + threadIdx.x;
    if (n < NN) {
        float mag   = expf(-expf(nu_log[n]));
        float phase = expf(theta_log[n]);
        g_lam[n]        = mag * cosf(phase);
        g_lam[NN + n]   = mag * sinf(phase);
        g_lam[2*NN + n] = sqrtf(fmaxf(1.0f - mag*mag, 0.0f));
    }
}

// ---------------------------------------------------------------------------
// fp32 -> (bf16 hi, bf16 lo)
// ---------------------------------------------------------------------------
__global__ void cvt_kernel(const float* __restrict__ src,
                           __nv_bfloat16* __restrict__ hi,
                           __nv_bfloat16* __restrict__ lo,
                           int n, float scale)
{
    int i = blockIdx.x * blockDim.x + threadIdx.x;
    if (i < n) {
        float v = src[i] * scale;
        __nv_bfloat16 h = __float2bfloat16(v);
        hi[i] = h;
        lo[i] = __float2bfloat16(v - __bfloat162float(h));
    }
}

// ---------------------------------------------------------------------------
// Sequential complex recurrence, blocked by 16 for MLP.
// ---------------------------------------------------------------------------
__global__ void scan_kernel(const float* __restrict__ hid_re,
                            const float* __restrict__ hid_im,
                            float* __restrict__ out)
{
    int idx = blockIdx.x * blockDim.x + threadIdx.x;   // 0..B*N-1
    int b = idx >> 10;
    int n = idx & (NN - 1);
    const float lre = g_lam[n];
    const float lim = g_lam[NN + n];
    float hr = hid_re[idx];
    float hi = hid_im[idx];
    size_t off = (size_t)b * SS * NN + n;
    for (int s0 = 0; s0 < SS; s0 += 16) {
        float ur[16], ui[16];
        #pragma unroll
        for (int q = 0; q < 16; q++) {
            ur[q] = g_u_re[off + (size_t)q * NN];
            ui[q] = g_u_im[off + (size_t)q * NN];
        }
        #pragma unroll
        for (int q = 0; q < 16; q++) {
            float nr = fmaf(lre, hr, fmaf(-lim, hi, ur[q]));
            float ni = fmaf(lre, hi, fmaf( lim, hr, ui[q]));
            __nv_bfloat16 rh = __float2bfloat16(nr);
            __nv_bfloat16 ih = __float2bfloat16(ni);
            size_t o = off + (size_t)q * NN;
            g_hsre_hi[o] = rh;
            g_hsre_lo[o] = __float2bfloat16(nr - __bfloat162float(rh));
            g_hsim_hi[o] = ih;
            g_hsim_lo[o] = __float2bfloat16(ni - __bfloat162float(ih));
            hr = nr; hi = ni;
        }
        off += (size_t)16 * NN;
    }
    out[(size_t)MM * DD + idx]         = hr;   // hf_re
    out[(size_t)MM * DD + BB*NN + idx] = hi;   // hf_im
}

// ---------------------------------------------------------------------------
// Fused pointwise: z = gelu(LN(LN(y) * gelu(LN(g)))) -> bf16 hi/lo
// ---------------------------------------------------------------------------
__device__ __forceinline__ float gelu_exact(float x)
{
    return 0.5f * x * (1.0f + erff(x * 0.70710678118654752f));
}
__device__ __forceinline__ void block_stats(float v0, float v1, float v2, float v3,
                                            float* sh, float& mu, float& rstd)
{
    float s  = v0 + v1 + v2 + v3;
    float s2 = v0*v0 + v1*v1 + v2*v2 + v3*v3;
    #pragma unroll
    for (int o = 16; o > 0; o >>= 1) {
        s  += __shfl_xor_sync(0xffffffffu, s,  o);
        s2 += __shfl_xor_sync(0xffffffffu, s2, o);
    }
    int w = threadIdx.x >> 5, l = threadIdx.x & 31;
    if (l == 0) { sh[w] = s; sh[8 + w] = s2; }
    __syncthreads();
    float ts = 0.f, ts2 = 0.f;
    #pragma unroll
    for (int i = 0; i < 8; i++) { ts += sh[i]; ts2 += sh[8 + i]; }
    __syncthreads();
    mu = ts * (1.0f / NN);
    float var = ts2 * (1.0f / NN) - mu * mu;
    rstd = rsqrtf(var + 1e-5f);
}

__global__ __launch_bounds__(256)
void pointwise_kernel(const float* __restrict__ y, const float* __restrict__ g)
{
    __shared__ float sh[16];
    const size_t base = (size_t)blockIdx.x * NN;
    const int t = threadIdx.x;

    float yv[4], gv[4];
    #pragma unroll
    for (int q = 0; q < 4; q++) {
        yv[q] = y[base + t + q*256];
        gv[q] = g[base + t + q*256];
    }
    float mu, rstd;
    block_stats(yv[0], yv[1], yv[2], yv[3], sh, mu, rstd);
    #pragma unroll
    for (int q = 0; q < 4; q++) yv[q] = (yv[q] - mu) * rstd;
    block_stats(gv[0], gv[1], gv[2], gv[3], sh, mu, rstd);
    #pragma unroll
    for (int q = 0; q < 4; q++) gv[q] = gelu_exact((gv[q] - mu) * rstd);
    #pragma unroll
    for (int q = 0; q < 4; q++) yv[q] *= gv[q];
    block_stats(yv[0], yv[1], yv[2], yv[3], sh, mu, rstd);
    #pragma unroll
    for (int q = 0; q < 4; q++) {
        float z = gelu_exact((yv[q] - mu) * rstd);
        __nv_bfloat16 zh = __float2bfloat16(z);
        g_z_hi[base + t + q*256] = zh;
        g_z_lo[base + t + q*256] = __float2bfloat16(z - __bfloat162float(zh));
    }
}

// ---------------------------------------------------------------------------
// Launch
// ---------------------------------------------------------------------------
extern "C" void kernel_launch(void* const* d_in, const int* in_sizes, int n_in,
                              void* d_out, int out_size)
{
    const float* x         = (const float*)d_in[0];
    const float* hidden_re = (const float*)d_in[1];
    const float* hidden_im = (const float*)d_in[2];
    const float* nu_log    = (const float*)d_in[3];
    const float* theta_log = (const float*)d_in[4];
    const float* W[7] = { (const float*)d_in[5],  (const float*)d_in[6],
                          (const float*)d_in[7],  (const float*)d_in[8],
                          (const float*)d_in[9],  (const float*)d_in[10],
                          (const float*)d_in[11] };
    float* out = (float*)d_out;

    float *u_re, *u_im, *ybuf, *gbuf, *lam;
    __nv_bfloat16 *x_hi, *x_lo, *hsre_hi, *hsre_lo, *hsim_hi, *hsim_lo,
                  *z_hi, *z_lo, *w_hi, *w_lo;
    cudaGetSymbolAddress((void**)&u_re,    g_u_re);
    cudaGetSymbolAddress((void**)&u_im,    g_u_im);
    cudaGetSymbolAddress((void**)&ybuf,    g_y);
    cudaGetSymbolAddress((void**)&gbuf,    g_g);
    cudaGetSymbolAddress((void**)&x_hi,    g_x_hi);
    cudaGetSymbolAddress((void**)&x_lo,    g_x_lo);
    cudaGetSymbolAddress((void**)&hsre_hi, g_hsre_hi);
    cudaGetSymbolAddress((void**)&hsre_lo, g_hsre_lo);
    cudaGetSymbolAddress((void**)&hsim_hi, g_hsim_hi);
    cudaGetSymbolAddress((void**)&hsim_lo, g_hsim_lo);
    cudaGetSymbolAddress((void**)&z_hi,    g_z_hi);
    cudaGetSymbolAddress((void**)&z_lo,    g_z_lo);
    cudaGetSymbolAddress((void**)&w_hi,    g_w_hi);
    cudaGetSymbolAddress((void**)&w_lo,    g_w_lo);
    cudaGetSymbolAddress((void**)&lam,     g_lam);
    const float* gamma = lam + 2*NN;

    cudaFuncSetAttribute(gemm_multi, cudaFuncAttributeMaxDynamicSharedMemorySize, GEMM_SMEM);
    cudaFuncSetAttribute(gemm_y,     cudaFuncAttributeMaxDynamicSharedMemorySize, GEMM_SMEM);

    // launches 0-4: params + the 4 conversions needed by the fused u/gate GEMM
    params_kernel<<<1, 1024>>>(nu_log, theta_log);
    cvt_kernel<<<(MM*DD + 255)/256, 256>>>(x, x_hi, x_lo, MM*DD, 1.0f);
    cvt_kernel<<<(WSZ + 255)/256, 256>>>(W[0], w_hi + 0*WSZ, w_lo + 0*WSZ, WSZ, 1.0f);
    cvt_kernel<<<(WSZ + 255)/256, 256>>>(W[1], w_hi + 1*WSZ, w_lo + 1*WSZ, WSZ, 1.0f);
    cvt_kernel<<<(WSZ + 255)/256, 256>>>(W[5], w_hi + 5*WSZ, w_lo + 5*WSZ, WSZ, 1.0f);

    // launch 5 (ncu -s 5 target): fused u_re / u_im / gate GEMM
    MultiParams mp;
    mp.a_hi = x_hi; mp.a_lo = x_lo;
    mp.jobs[0] = { w_hi + 0*WSZ, w_lo + 0*WSZ, u_re, gamma };
    mp.jobs[1] = { w_hi + 1*WSZ, w_lo + 1*WSZ, u_im, gamma };
    mp.jobs[2] = { w_hi + 5*WSZ, w_lo + 5*WSZ, gbuf, nullptr };
    gemm_multi<<<dim3(24, MM/128), 256, GEMM_SMEM>>>(mp, NN);

    // remaining weight conversions (overlap-free but off the critical profile slot)
    cvt_kernel<<<(WSZ + 255)/256, 256>>>(W[2], w_hi + 2*WSZ, w_lo + 2*WSZ, WSZ,  1.0f);
    cvt_kernel<<<(WSZ + 255)/256, 256>>>(W[3], w_hi + 3*WSZ, w_lo + 3*WSZ, WSZ, -1.0f); // -C_im
    cvt_kernel<<<(WSZ + 255)/256, 256>>>(W[4], w_hi + 4*WSZ, w_lo + 4*WSZ, WSZ,  1.0f);
    cvt_kernel<<<(WSZ + 255)/256, 256>>>(W[6], w_hi + 6*WSZ, w_lo + 6*WSZ, WSZ,  1.0f);

    // recurrence (writes hs hi/lo + final state)
    scan_kernel<<<(BB*NN)/256, 256>>>(hidden_re, hidden_im, out);

    // y = hs_re@C_re^T - hs_im@C_im^T + x@D_skip^T  (C_im pre-negated)
    YParams py;
    py.t[0] = { hsre_hi, hsre_lo, w_hi + 2*WSZ, w_lo + 2*WSZ };
    py.t[1] = { hsim_hi, hsim_lo, w_hi + 3*WSZ, w_lo + 3*WSZ };
    py.t[2] = { x_hi,    x_lo,    w_hi + 4*WSZ, w_lo + 4*WSZ };
    gemm_y<<<dim3(8, MM/128), 256, GEMM_SMEM>>>(py, ybuf, NN);

    // fused LN/GELU chain -> z hi/lo
    pointwise_kernel<<<MM, 256>>>(ybuf, gbuf);

    // out = z @ W_con^T
    MultiParams mo;
    mo.a_hi = z_hi; mo.a_lo = z_lo;
    mo.jobs[0] = { w_hi + 6*WSZ, w_lo + 6*WSZ, out, nullptr };
    gemm_multi<<<dim3(8, MM/128), 256, GEMM_SMEM>>>(mo, DD);
}